// round 1
// baseline (speedup 1.0000x reference)
#include <cuda_runtime.h>
#include <cuda_bf16.h>
#include <cstdint>

// ---------------------------------------------------------------------------
// SparseMiddleExtractor: dense-equivalent 5-conv chain, fp32, FFMA2 (f32x2).
//   conv0 : 3x3x3 SAME, 128->64, input&output masked, relu      D=41
//   down1 : (3,1,1) stride (2,1,1) VALID, 64->64, relu          D=41->20 (+mask maxpool)
//   subm1a: 3x3x3 SAME, 64->64, output masked (m2), relu        D=20
//   subm1b: 3x3x3 SAME, 64->64, output masked (m2), relu        D=20
//   down2 : (3,1,1) stride (2,1,1) VALID, 64->64, relu          D=20->9  -> d_out
// ---------------------------------------------------------------------------

typedef unsigned long long u64;

#define HW 16384  // 128*128

// ---------------- static device scratch (no allocation allowed) ------------
__device__ float g_x1[64 * 41 * HW];   // conv0 out / reused as subm1b out (x4)
__device__ float g_x2[64 * 20 * HW];   // down1 out
__device__ float g_x3[64 * 20 * HW];   // subm1a out
__device__ float g_m0[41 * HW];        // (mask > 0.5) as 0/1 float
__device__ float g_m2[20 * HW];        // downsampled active mask
__device__ float g_w0 [27 * 128 * 64]; // transposed [kd][kh][ci][kw][co]
__device__ float g_w1a[27 * 64 * 64];
__device__ float g_w1b[27 * 64 * 64];
__device__ float g_wd1[3 * 64 * 64];   // transposed [ci][kd][co]
__device__ float g_wd2[3 * 64 * 64];

// ---------------- f32x2 helpers ---------------------------------------------
__device__ __forceinline__ u64 pack2(float v) {
    u64 r;
    asm("mov.b64 %0, {%1, %1};" : "=l"(r) : "r"(__float_as_uint(v)));
    return r;
}
__device__ __forceinline__ void ffma2(u64& acc, u64 a, u64 b) {
    asm("fma.rn.f32x2 %0, %1, %2, %0;" : "+l"(acc) : "l"(a), "l"(b));
}
__device__ __forceinline__ float lo2(u64 v) { return __uint_as_float((unsigned)v); }
__device__ __forceinline__ float hi2(u64 v) { return __uint_as_float((unsigned)(v >> 32)); }

// ---------------- prep: 0/1 mask + weight transposes ------------------------
__global__ void prep_kernel(const float* __restrict__ mask,
                            const float* __restrict__ W0,
                            const float* __restrict__ Wd1,
                            const float* __restrict__ W1a,
                            const float* __restrict__ W1b,
                            const float* __restrict__ Wd2)
{
    const int idx = blockIdx.x * blockDim.x + threadIdx.x;
    const int stride = gridDim.x * blockDim.x;

    for (int i = idx; i < 41 * HW; i += stride)
        g_m0[i] = mask[i] > 0.5f ? 1.0f : 0.0f;

    // dst[(((kd*3+kh)*128 + ci)*3 + kw)*64 + co] = W0[(co*128+ci)*27 + kd*9+kh*3+kw]
    for (int i = idx; i < 64 * 128 * 27; i += stride) {
        int co = i & 63; int t = i >> 6;
        int kw = t % 3; t /= 3;
        int ci = t & 127; t >>= 7;
        int kh = t % 3; int kd = t / 3;
        g_w0[i] = W0[(co * 128 + ci) * 27 + kd * 9 + kh * 3 + kw];
    }
    for (int i = idx; i < 64 * 64 * 27; i += stride) {
        int co = i & 63; int t = i >> 6;
        int kw = t % 3; t /= 3;
        int ci = t & 63; t >>= 6;
        int kh = t % 3; int kd = t / 3;
        int src = (co * 64 + ci) * 27 + kd * 9 + kh * 3 + kw;
        g_w1a[i] = W1a[src];
        g_w1b[i] = W1b[src];
    }
    // dst[(ci*3+kd)*64+co] = W[(co*64+ci)*3 + kd]
    for (int i = idx; i < 64 * 64 * 3; i += stride) {
        int co = i & 63; int t = i >> 6;
        int kd = t % 3; int ci = t / 3;
        int src = (co * 64 + ci) * 3 + kd;
        g_wd1[i] = Wd1[src];
        g_wd2[i] = Wd2[src];
    }
}

// ---------------- 3x3x3 SAME conv, relu, masked -----------------------------
// Block = one (d, h). 256 threads produce 64 cout x 128 w.
// Thread (warp, lane): co pair-group = warp*8 .. warp*8+7 ; w = lane + 32*j.
template <int CIN, bool MASK_IN>
__global__ void __launch_bounds__(256)
subm_conv_kernel(const float* __restrict__ in,      // [CIN, D, 128, 128]
                 const float* __restrict__ wt,      // [3][3][CIN][3][64]
                 const float* __restrict__ inmask,  // [D,128,128] 0/1 (if MASK_IN)
                 const float* __restrict__ outmask, // [D,128,128] 0/1
                 float* __restrict__ out,           // [64, D, 128, 128]
                 int D)
{
    const int d = blockIdx.y;
    const int h = blockIdx.x;
    const int tid = threadIdx.x;
    const int lane = tid & 31;
    const int warp = tid >> 5;
    const int co_base = warp * 8;

    __shared__ __align__(16) float in_s[8][132];    // 8 cin rows, w = -1..128 at idx 0..129
    __shared__ __align__(16) float w_s[8][3][64];   // [cin][kw][co]

    u64 acc[4][4];                                  // [co_pair][j]
    #pragma unroll
    for (int p = 0; p < 4; ++p)
        #pragma unroll
        for (int j = 0; j < 4; ++j) acc[p][j] = 0ULL;

    const size_t plane = (size_t)D * HW;

    for (int kd = 0; kd < 3; ++kd) {
        const int din = d + kd - 1;
        if (din < 0 || din >= D) continue;
        for (int kh = 0; kh < 3; ++kh) {
            const int hin = h + kh - 1;
            if (hin < 0 || hin >= 128) continue;

            const float* inb  = in + (size_t)din * HW + hin * 128;
            const float* mrow = MASK_IN ? (inmask + (size_t)din * HW + hin * 128) : nullptr;
            const float* wb   = wt + (size_t)((kd * 3 + kh) * CIN) * 192;

            for (int c0 = 0; c0 < CIN; c0 += 8) {
                __syncthreads();
                // stage 8 input rows (with w halo), masked if requested
                #pragma unroll 1
                for (int i = tid; i < 8 * 130; i += 256) {
                    int c = i / 130;
                    int p = i - 130 * c;
                    int w = p - 1;
                    float v = 0.0f;
                    if ((unsigned)w < 128u) {
                        v = inb[(size_t)(c0 + c) * plane + w];
                        if (MASK_IN) v *= mrow[w];
                    }
                    in_s[c][p] = v;
                }
                // stage weights: contiguous 1536 floats
                const float* ws = wb + c0 * 192;
                #pragma unroll 1
                for (int i = tid; i < 1536; i += 256)
                    ((float*)w_s)[i] = ws[i];
                __syncthreads();

                #pragma unroll
                for (int c = 0; c < 8; ++c) {
                    u64 wp[3][4];
                    #pragma unroll
                    for (int kw = 0; kw < 3; ++kw)
                        #pragma unroll
                        for (int p = 0; p < 4; ++p)
                            wp[kw][p] = *reinterpret_cast<const u64*>(
                                &w_s[c][kw][co_base + 2 * p]);
                    #pragma unroll
                    for (int j = 0; j < 4; ++j) {
                        const int base = lane + 32 * j;
                        u64 ip0 = pack2(in_s[c][base]);
                        u64 ip1 = pack2(in_s[c][base + 1]);
                        u64 ip2 = pack2(in_s[c][base + 2]);
                        #pragma unroll
                        for (int p = 0; p < 4; ++p) {
                            ffma2(acc[p][j], wp[0][p], ip0);
                            ffma2(acc[p][j], wp[1][p], ip1);
                            ffma2(acc[p][j], wp[2][p], ip2);
                        }
                    }
                }
            }
        }
    }

    const float* om = outmask + (size_t)d * HW + h * 128;
    #pragma unroll
    for (int j = 0; j < 4; ++j) {
        const int w = lane + 32 * j;
        const float mv = om[w];
        #pragma unroll
        for (int p = 0; p < 4; ++p) {
            const int co0 = co_base + 2 * p;
            float v0 = lo2(acc[p][j]) * mv;
            float v1 = hi2(acc[p][j]) * mv;
            out[((size_t)co0 * D + d) * HW + h * 128 + w]       = fmaxf(v0, 0.0f);
            out[((size_t)(co0 + 1) * D + d) * HW + h * 128 + w] = fmaxf(v1, 0.0f);
        }
    }
}

// ---------------- (3,1,1) stride-(2,1,1) conv, relu -------------------------
template <bool MAKE_MASK>
__global__ void __launch_bounds__(256)
down_conv_kernel(const float* __restrict__ in, int Din,
                 const float* __restrict__ wt,   // [ci][kd][co]
                 float* __restrict__ out, int Dout,
                 const float* __restrict__ m_in,
                 float* __restrict__ m_out)
{
    const int dp = blockIdx.y;
    const int h = blockIdx.x;
    const int tid = threadIdx.x;
    const int lane = tid & 31;
    const int warp = tid >> 5;
    const int co_base = warp * 8;
    const int d0 = 2 * dp;
    const size_t rowoff = (size_t)h * 128;

    __shared__ __align__(16) float in_s[8][3][128];
    __shared__ __align__(16) float w_s[8][3][64];

    float acc[8][4];
    #pragma unroll
    for (int co = 0; co < 8; ++co)
        #pragma unroll
        for (int j = 0; j < 4; ++j) acc[co][j] = 0.0f;

    for (int c0 = 0; c0 < 64; c0 += 8) {
        __syncthreads();
        #pragma unroll 1
        for (int i = tid; i < 3072; i += 256) {
            int c = i / 384;
            int r = i - 384 * c;
            int kd = r >> 7;
            int w = r & 127;
            in_s[c][kd][w] = in[((size_t)(c0 + c) * Din + d0 + kd) * HW + rowoff + w];
        }
        #pragma unroll 1
        for (int i = tid; i < 1536; i += 256)
            ((float*)w_s)[i] = wt[c0 * 192 + i];
        __syncthreads();

        #pragma unroll
        for (int c = 0; c < 8; ++c) {
            float wv[3][8];
            #pragma unroll
            for (int kd = 0; kd < 3; ++kd)
                #pragma unroll
                for (int co = 0; co < 8; ++co)
                    wv[kd][co] = w_s[c][kd][co_base + co];
            #pragma unroll
            for (int j = 0; j < 4; ++j) {
                const int w = lane + 32 * j;
                float i0 = in_s[c][0][w];
                float i1 = in_s[c][1][w];
                float i2 = in_s[c][2][w];
                #pragma unroll
                for (int co = 0; co < 8; ++co)
                    acc[co][j] += wv[0][co] * i0 + wv[1][co] * i1 + wv[2][co] * i2;
            }
        }
    }

    if (MAKE_MASK && tid < 128) {
        const size_t b = rowoff + tid;
        float v = fmaxf(m_in[(size_t)d0 * HW + b],
                        fmaxf(m_in[(size_t)(d0 + 1) * HW + b],
                              m_in[(size_t)(d0 + 2) * HW + b]));
        m_out[(size_t)dp * HW + b] = v;
    }

    #pragma unroll
    for (int j = 0; j < 4; ++j) {
        const int w = lane + 32 * j;
        #pragma unroll
        for (int co = 0; co < 8; ++co)
            out[((size_t)(co_base + co) * Dout + dp) * HW + rowoff + w] =
                fmaxf(acc[co][j], 0.0f);
    }
}

// ---------------------------------------------------------------------------
extern "C" void kernel_launch(void* const* d_in, const int* in_sizes, int n_in,
                              void* d_out, int out_size)
{
    const float* feat = (const float*)d_in[0];
    const float* mask = (const float*)d_in[1];
    const float* W0   = (const float*)d_in[2];
    const float* Wd1  = (const float*)d_in[3];
    const float* W1a  = (const float*)d_in[4];
    const float* W1b  = (const float*)d_in[5];
    const float* Wd2  = (const float*)d_in[6];
    float* out = (float*)d_out;

    void* p;
    cudaGetSymbolAddress(&p, g_x1);  float* x1  = (float*)p;
    cudaGetSymbolAddress(&p, g_x2);  float* x2  = (float*)p;
    cudaGetSymbolAddress(&p, g_x3);  float* x3  = (float*)p;
    cudaGetSymbolAddress(&p, g_m0);  float* m0  = (float*)p;
    cudaGetSymbolAddress(&p, g_m2);  float* m2  = (float*)p;
    cudaGetSymbolAddress(&p, g_w0);  float* w0  = (float*)p;
    cudaGetSymbolAddress(&p, g_w1a); float* w1a = (float*)p;
    cudaGetSymbolAddress(&p, g_w1b); float* w1b = (float*)p;
    cudaGetSymbolAddress(&p, g_wd1); float* wd1 = (float*)p;
    cudaGetSymbolAddress(&p, g_wd2); float* wd2 = (float*)p;
    float* x4 = x1;  // g_x1 is dead after down1; reuse for subm1b output

    prep_kernel<<<256, 256>>>(mask, W0, Wd1, W1a, W1b, Wd2);

    // conv0: 128->64, masked in & out
    subm_conv_kernel<128, true><<<dim3(128, 41), 256>>>(feat, w0, m0, m0, x1, 41);
    // down1 + mask maxpool
    down_conv_kernel<true><<<dim3(128, 20), 256>>>(x1, 41, wd1, x2, 20, m0, m2);
    // subm1a / subm1b
    subm_conv_kernel<64, false><<<dim3(128, 20), 256>>>(x2, w1a, nullptr, m2, x3, 20);
    subm_conv_kernel<64, false><<<dim3(128, 20), 256>>>(x3, w1b, nullptr, m2, x4, 20);
    // down2 -> final output
    down_conv_kernel<false><<<dim3(128, 9), 256>>>(x4, 20, wd2, out, 9, nullptr, nullptr);
}

// round 4
// speedup vs baseline: 2.2117x; 2.2117x over previous
#include <cuda_runtime.h>
#include <cuda_bf16.h>
#include <cstdint>

typedef unsigned int u32;
typedef unsigned long long u64;

#define HW 16384  // 128*128

// ============================================================================
// Static device scratch
// ============================================================================
__device__ __align__(16) __nv_bfloat16 g_x0h[41 * HW * 128];
__device__ __align__(16) __nv_bfloat16 g_x0l[41 * HW * 128];
__device__ __align__(16) __nv_bfloat16 g_x1h[41 * HW * 64];
__device__ __align__(16) __nv_bfloat16 g_x1l[41 * HW * 64];
__device__ __align__(16) __nv_bfloat16 g_x2h[20 * HW * 64];
__device__ __align__(16) __nv_bfloat16 g_x2l[20 * HW * 64];
__device__ __align__(16) __nv_bfloat16 g_x3h[20 * HW * 64];
__device__ __align__(16) __nv_bfloat16 g_x3l[20 * HW * 64];
__device__ float g_m0[41 * HW];
__device__ float g_m2[20 * HW];
// Weights: per-chunk [64 co][64 ci] bf16, PRE-SWIZZLED (SW128 XOR), hi/lo
__device__ __align__(16) __nv_bfloat16 g_B0h[54 * 4096], g_B0l[54 * 4096];
__device__ __align__(16) __nv_bfloat16 g_B1ah[27 * 4096], g_B1al[27 * 4096];
__device__ __align__(16) __nv_bfloat16 g_B1bh[27 * 4096], g_B1bl[27 * 4096];
__device__ __align__(16) __nv_bfloat16 g_Bd1h[3 * 4096], g_Bd1l[3 * 4096];
__device__ __align__(16) __nv_bfloat16 g_Bd2h[3 * 4096], g_Bd2l[3 * 4096];

// ============================================================================
// PTX helpers (sm_80-era: mma.sync / ldmatrix / cp.async — legal on sm_103)
// ============================================================================
__device__ __forceinline__ u32 smem_u32(const void* p) {
    u32 a;
    asm("{ .reg .u64 t; cvta.to.shared.u64 t, %1; cvt.u32.u64 %0, t; }"
        : "=r"(a) : "l"(p));
    return a;
}
__device__ __forceinline__ void cp_async16(u32 dst, const void* src, bool valid) {
    int sz = valid ? 16 : 0;
    asm volatile("cp.async.cg.shared.global [%0], [%1], 16, %2;"
                 :: "r"(dst), "l"(src), "r"(sz) : "memory");
}
__device__ __forceinline__ void cp_commit() {
    asm volatile("cp.async.commit_group;" ::: "memory");
}
template <int N>
__device__ __forceinline__ void cp_wait() {
    asm volatile("cp.async.wait_group %0;" :: "n"(N) : "memory");
}
#define LDMX4(r0, r1, r2, r3, addr) \
    asm volatile("ldmatrix.sync.aligned.m8n8.x4.shared.b16 {%0,%1,%2,%3}, [%4];" \
                 : "=r"(r0), "=r"(r1), "=r"(r2), "=r"(r3) : "r"(addr))

__device__ __forceinline__ void mma_bf16(float* c, const u32* a, const u32* b) {
    asm volatile(
        "mma.sync.aligned.m16n8k16.row.col.f32.bf16.bf16.f32 "
        "{%0,%1,%2,%3}, {%4,%5,%6,%7}, {%8,%9}, {%0,%1,%2,%3};"
        : "+f"(c[0]), "+f"(c[1]), "+f"(c[2]), "+f"(c[3])
        : "r"(a[0]), "r"(a[1]), "r"(a[2]), "r"(a[3]), "r"(b[0]), "r"(b[1]));
}

__device__ __forceinline__ void split_bf16(float v, __nv_bfloat16& h, __nv_bfloat16& l) {
    h = __float2bfloat16_rn(v);
    l = __float2bfloat16_rn(v - __bfloat162float(h));
}
// swizzled bf16 index within a 64x64 tile for (row=co, col=ci), 128B rows
__device__ __forceinline__ int swidx(int co, int ci) {
    int ub = co * 128 + (ci >> 3) * 16;
    int sw = ub ^ ((ub >> 3) & 0x70);
    return (sw >> 1) + (ci & 7);
}
__device__ __forceinline__ u32 swz(u32 b) { return b ^ ((b >> 3) & 0x70); }

// ============================================================================
// Prep kernels
// ============================================================================
__global__ void prep_weights(const float* __restrict__ W0,
                             const float* __restrict__ Wd1,
                             const float* __restrict__ W1a,
                             const float* __restrict__ W1b,
                             const float* __restrict__ Wd2,
                             const float* __restrict__ mask)
{
    const int gid = blockIdx.x * blockDim.x + threadIdx.x;
    const int gs = gridDim.x * blockDim.x;

    for (int i = gid; i < 54 * 4096; i += gs) {
        int chunk = i >> 12, r = i & 4095, co = r >> 6, ci = r & 63;
        int cc = chunk & 1, tap = chunk >> 1;
        int kw = tap % 3, kh = (tap / 3) % 3, kd = tap / 9;
        float v = W0[(size_t)(co * 128 + cc * 64 + ci) * 27 + kd * 9 + kh * 3 + kw];
        __nv_bfloat16 h, l; split_bf16(v, h, l);
        int dst = chunk * 4096 + swidx(co, ci);
        g_B0h[dst] = h; g_B0l[dst] = l;
    }
    for (int i = gid; i < 27 * 4096; i += gs) {
        int chunk = i >> 12, r = i & 4095, co = r >> 6, ci = r & 63;
        int kw = chunk % 3, kh = (chunk / 3) % 3, kd = chunk / 9;
        size_t src = (size_t)(co * 64 + ci) * 27 + kd * 9 + kh * 3 + kw;
        int dst = chunk * 4096 + swidx(co, ci);
        __nv_bfloat16 h, l;
        split_bf16(W1a[src], h, l); g_B1ah[dst] = h; g_B1al[dst] = l;
        split_bf16(W1b[src], h, l); g_B1bh[dst] = h; g_B1bl[dst] = l;
    }
    for (int i = gid; i < 3 * 4096; i += gs) {
        int chunk = i >> 12, r = i & 4095, co = r >> 6, ci = r & 63;
        size_t src = (size_t)(co * 64 + ci) * 3 + chunk;
        int dst = chunk * 4096 + swidx(co, ci);
        __nv_bfloat16 h, l;
        split_bf16(Wd1[src], h, l); g_Bd1h[dst] = h; g_Bd1l[dst] = l;
        split_bf16(Wd2[src], h, l); g_Bd2h[dst] = h; g_Bd2l[dst] = l;
    }
    for (int i = gid; i < 20 * HW; i += gs) {
        int dp = i >> 14, r = i & 16383;
        float a = mask[(size_t)(2 * dp) * HW + r];
        float b = mask[(size_t)(2 * dp + 1) * HW + r];
        float c = mask[(size_t)(2 * dp + 2) * HW + r];
        g_m2[i] = (fmaxf(a, fmaxf(b, c)) > 0.5f) ? 1.0f : 0.0f;
    }
}

__global__ void __launch_bounds__(256) conv0_pre(const float* __restrict__ feat,
                                                 const float* __restrict__ mask)
{
    const int h = blockIdx.x, d = blockIdx.y;
    const int tid = threadIdx.x;
    __shared__ float t[32][129];
    __shared__ float mrow[128];

    const size_t row0 = ((size_t)d * 128 + h) * 128;
    if (tid < 128) {
        float mv = mask[row0 + tid] > 0.5f ? 1.0f : 0.0f;
        mrow[tid] = mv;
        g_m0[row0 + tid] = mv;
    }
    __syncthreads();

    for (int cc = 0; cc < 4; ++cc) {
        #pragma unroll 1
        for (int i = tid; i < 32 * 128; i += 256) {
            int ci = i >> 7, w = i & 127;
            t[ci][w] = feat[((size_t)(cc * 32 + ci) * 41 + d) * HW + h * 128 + w];
        }
        __syncthreads();
        #pragma unroll 1
        for (int i = tid; i < 128 * 16; i += 256) {
            int w = i >> 4, p = i & 15;
            float mv = mrow[w];
            float v0 = t[p * 2][w] * mv;
            float v1 = t[p * 2 + 1][w] * mv;
            __nv_bfloat16 h0, l0, h1, l1;
            split_bf16(v0, h0, l0);
            split_bf16(v1, h1, l1);
            __nv_bfloat162 hh(h0, h1), ll(l0, l1);
            size_t base = (row0 + w) * 128 + cc * 32;
            *(__nv_bfloat162*)(g_x0h + base + p * 2) = hh;
            *(__nv_bfloat162*)(g_x0l + base + p * 2) = ll;
        }
        __syncthreads();
    }
}

// ============================================================================
// Implicit-GEMM conv via mma.sync (HMMA), bf16 hi/lo 3-term split.
// CTA = one (dz,h) output row: M=128(w) x N=64(co), K = taps x 64ci chunks.
// 8 warps: warp_m = wid&3 (m32), warp_n = wid>>2 (n32). acc in registers.
// Double-buffered smem staged by cp.async; ldmatrix with SW128 XOR swizzle.
// ============================================================================
#define ABYTES 32768                 // A hi+lo (128x64 bf16 x2)
#define BBYTES 16384                 // B hi+lo (64x64 bf16 x2)
#define BUFB (ABYTES + BBYTES)       // 48KB
#define SMEM_BYTES (2 * BUFB)        // 96KB

template <int CC, bool K333, bool OMASK, bool FP32OUT>
__global__ void __launch_bounds__(256)
conv_mma_kernel(const __nv_bfloat16* __restrict__ in_hi,
                const __nv_bfloat16* __restrict__ in_lo,
                const __nv_bfloat16* __restrict__ w_hi,
                const __nv_bfloat16* __restrict__ w_lo,
                const float* __restrict__ omask,
                __nv_bfloat16* __restrict__ out_hi,
                __nv_bfloat16* __restrict__ out_lo,
                float* __restrict__ out_f32,
                int Din, int Dout)
{
    extern __shared__ char smem[];
    const u32 smem_base = smem_u32(smem);
    const int tid = threadIdx.x;
    const int wid = tid >> 5;
    const int lane = tid & 31;
    const int h = blockIdx.x;
    const int dz = blockIdx.y;
    const int CITOT = CC * 64;
    const int warp_m = wid & 3;
    const int warp_n = wid >> 2;

    __shared__ int s_din[54];
    __shared__ int s_aux[54];   // hin | kw<<8 | cc<<12 | widx<<16
    __shared__ int s_n;
    __shared__ float s_mask[128];

    if (tid == 0) {
        int n = 0;
        if (K333) {
            for (int kd = 0; kd < 3; ++kd) {
                int din = dz + kd - 1;
                if (din < 0 || din >= Din) continue;
                for (int kh = 0; kh < 3; ++kh) {
                    int hin = h + kh - 1;
                    if ((unsigned)hin > 127u) continue;
                    for (int cc = 0; cc < CC; ++cc)
                        for (int kw = 0; kw < 3; ++kw) {
                            int widx = ((kd * 3 + kh) * 3 + kw) * CC + cc;
                            s_din[n] = din;
                            s_aux[n] = hin | (kw << 8) | (cc << 12) | (widx << 16);
                            ++n;
                        }
                }
            }
        } else {
            for (int kd = 0; kd < 3; ++kd) {
                s_din[n] = 2 * dz + kd;
                s_aux[n] = h | (1 << 8) | (kd << 16);
                ++n;
            }
        }
        s_n = n;
    }
    if (OMASK && tid < 128)
        s_mask[tid] = omask[((size_t)dz * 128 + h) * 128 + tid];
    __syncthreads();
    const int nch = s_n;

    // per-thread staging constants
    const int sp = tid >> 7;            // 0 = hi, 1 = lo split
    const int mrow = tid & 127;         // A row staged by this thread
    const __nv_bfloat16* xin = sp ? in_lo : in_hi;
    const __nv_bfloat16* wsrc = sp ? w_lo : w_hi;

    // precomputed swizzled A-row store offsets (full-offset swizzle: correct)
    u32 a_st[8];
    #pragma unroll
    for (int u = 0; u < 8; ++u)
        a_st[u] = swz(mrow * 128 + u * 16);

    // ldmatrix addressing: addr = rowbase + ((col_byte + ko) ^ sxnibble).
    // col_byte + ko <= 112 < 128, XOR keeps it inside the 128B row: in-bounds.
    u32 a_row[2], a_sx[2];
    #pragma unroll
    for (int mt = 0; mt < 2; ++mt) {
        int row = warp_m * 32 + mt * 16 + (lane & 7) + ((lane >> 3) & 1) * 8;
        a_row[mt] = (u32)row * 128;
        a_sx[mt] = (u32)(row & 7) << 4;
    }
    const u32 a_c = (u32)(lane >> 4) * 16;

    u32 b_row[2], b_sx[2];
    #pragma unroll
    for (int nh = 0; nh < 2; ++nh) {
        int rown = warp_n * 32 + nh * 16 + (lane & 7) + (lane >> 4) * 8;
        b_row[nh] = (u32)rown * 128;
        b_sx[nh] = (u32)(rown & 7) << 4;
    }
    const u32 b_c = (u32)((lane >> 3) & 1) * 16;

    float acc[2][4][4];
    #pragma unroll
    for (int mt = 0; mt < 2; ++mt)
        #pragma unroll
        for (int nt = 0; nt < 4; ++nt)
            #pragma unroll
            for (int q = 0; q < 4; ++q) acc[mt][nt][q] = 0.0f;

    // ---- staging (cp.async) ----
    auto stage = [&](int i, int buf) {
        const int din = s_din[i];
        const int aux = s_aux[i];
        const int hin = aux & 255;
        const int kw = (aux >> 8) & 15;
        const int cc = (aux >> 12) & 15;
        const int widx = aux >> 16;
        const u32 abase = smem_base + buf * BUFB + sp * 16384;
        const int win = K333 ? (mrow + kw - 1) : mrow;
        const bool valid = !K333 || ((unsigned)win < 128u);
        const char* src = (const char*)(xin +
            (((size_t)din * 128 + hin) * 128 + (valid ? win : 0)) * CITOT + cc * 64);
        #pragma unroll
        for (int u = 0; u < 8; ++u)
            cp_async16(abase + a_st[u], src + u * 16, valid);

        const u32 bbase = smem_base + buf * BUFB + ABYTES + sp * 8192;
        const char* gb = (const char*)(wsrc + (size_t)widx * 4096);
        const int j = tid & 127;
        #pragma unroll
        for (int u = 0; u < 4; ++u)
            cp_async16(bbase + (j + u * 128) * 16, gb + (j + u * 128) * 16, true);
        cp_commit();
    };

    stage(0, 0);
    for (int i = 0; i < nch; ++i) {
        const int buf = i & 1;
        if (i + 1 < nch) { stage(i + 1, buf ^ 1); cp_wait<1>(); }
        else             { cp_wait<0>(); }
        __syncthreads();

        const u32 ahi = smem_base + buf * BUFB;
        const u32 alo = ahi + 16384;
        const u32 bhi = smem_base + buf * BUFB + ABYTES;
        const u32 blo = bhi + 8192;

        #pragma unroll
        for (int k16 = 0; k16 < 4; ++k16) {
            const u32 ko = k16 * 32;
            u32 A0[2][4], A1[2][4];
            #pragma unroll
            for (int mt = 0; mt < 2; ++mt) {
                const u32 aoff = a_row[mt] + ((a_c + ko) ^ a_sx[mt]);
                LDMX4(A0[mt][0], A0[mt][1], A0[mt][2], A0[mt][3], ahi + aoff);
                LDMX4(A1[mt][0], A1[mt][1], A1[mt][2], A1[mt][3], alo + aoff);
            }
            u32 B0[4][2], B1[4][2];
            #pragma unroll
            for (int nh = 0; nh < 2; ++nh) {
                const u32 boff = b_row[nh] + ((b_c + ko) ^ b_sx[nh]);
                LDMX4(B0[2*nh][0], B0[2*nh][1], B0[2*nh+1][0], B0[2*nh+1][1],
                      bhi + boff);
                LDMX4(B1[2*nh][0], B1[2*nh][1], B1[2*nh+1][0], B1[2*nh+1][1],
                      blo + boff);
            }
            #pragma unroll
            for (int mt = 0; mt < 2; ++mt)
                #pragma unroll
                for (int nt = 0; nt < 4; ++nt) {
                    mma_bf16(acc[mt][nt], A0[mt], B0[nt]);  // hi*hi
                    mma_bf16(acc[mt][nt], A0[mt], B1[nt]);  // hi*lo
                    mma_bf16(acc[mt][nt], A1[mt], B0[nt]);  // lo*hi
                }
        }
        __syncthreads();
    }

    // ---- epilogue ----
    const int g = lane >> 2, tg = lane & 3;
    #pragma unroll
    for (int mt = 0; mt < 2; ++mt) {
        #pragma unroll
        for (int half = 0; half < 2; ++half) {
            const int m = warp_m * 32 + mt * 16 + g + half * 8;
            const float mv = OMASK ? s_mask[m] : 1.0f;
            const size_t row = ((size_t)dz * 128 + h) * 128 + m;
            #pragma unroll
            for (int nt = 0; nt < 4; ++nt) {
                const int n0 = warp_n * 32 + nt * 8 + tg * 2;
                float v0 = fmaxf(acc[mt][nt][half * 2 + 0] * mv, 0.0f);
                float v1 = fmaxf(acc[mt][nt][half * 2 + 1] * mv, 0.0f);
                if (FP32OUT) {
                    out_f32[((size_t)n0 * Dout + dz) * HW + h * 128 + m] = v0;
                    out_f32[((size_t)(n0 + 1) * Dout + dz) * HW + h * 128 + m] = v1;
                } else {
                    __nv_bfloat16 h0, l0, h1, l1;
                    split_bf16(v0, h0, l0);
                    split_bf16(v1, h1, l1);
                    __nv_bfloat162 hh(h0, h1), ll(l0, l1);
                    *(u32*)(out_hi + row * 64 + n0) = *(u32*)&hh;
                    *(u32*)(out_lo + row * 64 + n0) = *(u32*)&ll;
                }
            }
        }
    }
}

// ============================================================================
extern "C" void kernel_launch(void* const* d_in, const int* in_sizes, int n_in,
                              void* d_out, int out_size)
{
    const float* feat = (const float*)d_in[0];
    const float* mask = (const float*)d_in[1];
    const float* W0   = (const float*)d_in[2];
    const float* Wd1  = (const float*)d_in[3];
    const float* W1a  = (const float*)d_in[4];
    const float* W1b  = (const float*)d_in[5];
    const float* Wd2  = (const float*)d_in[6];
    float* out = (float*)d_out;

    void* p;
    #define SYM(v, s) cudaGetSymbolAddress(&p, s); auto* v = (decltype(&s[0]))p;
    SYM(x0h, g_x0h) SYM(x0l, g_x0l)
    SYM(x1h, g_x1h) SYM(x1l, g_x1l)
    SYM(x2h, g_x2h) SYM(x2l, g_x2l)
    SYM(x3h, g_x3h) SYM(x3l, g_x3l)
    SYM(m0, g_m0)   SYM(m2, g_m2)
    SYM(b0h, g_B0h)   SYM(b0l, g_B0l)
    SYM(b1ah, g_B1ah) SYM(b1al, g_B1al)
    SYM(b1bh, g_B1bh) SYM(b1bl, g_B1bl)
    SYM(bd1h, g_Bd1h) SYM(bd1l, g_Bd1l)
    SYM(bd2h, g_Bd2h) SYM(bd2l, g_Bd2l)
    #undef SYM

    cudaFuncSetAttribute(conv_mma_kernel<2, true, true, false>,
                         cudaFuncAttributeMaxDynamicSharedMemorySize, SMEM_BYTES);
    cudaFuncSetAttribute(conv_mma_kernel<1, true, true, false>,
                         cudaFuncAttributeMaxDynamicSharedMemorySize, SMEM_BYTES);
    cudaFuncSetAttribute(conv_mma_kernel<1, false, false, false>,
                         cudaFuncAttributeMaxDynamicSharedMemorySize, SMEM_BYTES);
    cudaFuncSetAttribute(conv_mma_kernel<1, false, false, true>,
                         cudaFuncAttributeMaxDynamicSharedMemorySize, SMEM_BYTES);

    prep_weights<<<264, 256>>>(W0, Wd1, W1a, W1b, Wd2, mask);
    conv0_pre<<<dim3(128, 41), 256>>>(feat, mask);

    // conv0: 128->64, 3x3x3 SAME, output masked by m0 (input pre-masked)
    conv_mma_kernel<2, true, true, false><<<dim3(128, 41), 256, SMEM_BYTES>>>(
        x0h, x0l, b0h, b0l, m0, x1h, x1l, nullptr, 41, 41);
    // down1: (3,1,1)/stride(2,1,1), relu
    conv_mma_kernel<1, false, false, false><<<dim3(128, 20), 256, SMEM_BYTES>>>(
        x1h, x1l, bd1h, bd1l, nullptr, x2h, x2l, nullptr, 41, 20);
    // subm1a / subm1b: 3x3x3 SAME, output masked by m2
    conv_mma_kernel<1, true, true, false><<<dim3(128, 20), 256, SMEM_BYTES>>>(
        x2h, x2l, b1ah, b1al, m2, x3h, x3l, nullptr, 20, 20);
    conv_mma_kernel<1, true, true, false><<<dim3(128, 20), 256, SMEM_BYTES>>>(
        x3h, x3l, b1bh, b1bl, m2, x1h, x1l, nullptr, 20, 20);
    // down2 -> fp32 NCDHW output
    conv_mma_kernel<1, false, false, true><<<dim3(128, 9), 256, SMEM_BYTES>>>(
        x1h, x1l, bd2h, bd2l, nullptr, nullptr, nullptr, out, 20, 9);
}

// round 5
// speedup vs baseline: 3.3502x; 1.5148x over previous
#include <cuda_runtime.h>
#include <cuda_bf16.h>
#include <cstdint>

typedef unsigned int u32;
typedef unsigned long long u64;

#define HW 16384  // 128*128

// ============================================================================
// Static device scratch
// ============================================================================
__device__ __align__(16) __nv_bfloat16 g_x0h[41 * HW * 128];
__device__ __align__(16) __nv_bfloat16 g_x0l[41 * HW * 128];
__device__ __align__(16) __nv_bfloat16 g_x1h[41 * HW * 64];
__device__ __align__(16) __nv_bfloat16 g_x1l[41 * HW * 64];
__device__ __align__(16) __nv_bfloat16 g_x2h[20 * HW * 64];
__device__ __align__(16) __nv_bfloat16 g_x2l[20 * HW * 64];
__device__ __align__(16) __nv_bfloat16 g_x3h[20 * HW * 64];
__device__ __align__(16) __nv_bfloat16 g_x3l[20 * HW * 64];
__device__ float g_m0[41 * HW];
__device__ float g_m2[20 * HW];
// Weights: per-chunk [64 co][64 ci] bf16, PRE-SWIZZLED (SW128 XOR), hi/lo
__device__ __align__(16) __nv_bfloat16 g_B0h[54 * 4096], g_B0l[54 * 4096];
__device__ __align__(16) __nv_bfloat16 g_B1ah[27 * 4096], g_B1al[27 * 4096];
__device__ __align__(16) __nv_bfloat16 g_B1bh[27 * 4096], g_B1bl[27 * 4096];
__device__ __align__(16) __nv_bfloat16 g_Bd1h[3 * 4096], g_Bd1l[3 * 4096];
__device__ __align__(16) __nv_bfloat16 g_Bd2h[3 * 4096], g_Bd2l[3 * 4096];

// ============================================================================
// PTX helpers
// ============================================================================
__device__ __forceinline__ u32 smem_u32(const void* p) {
    u32 a;
    asm("{ .reg .u64 t; cvta.to.shared.u64 t, %1; cvt.u32.u64 %0, t; }"
        : "=r"(a) : "l"(p));
    return a;
}
__device__ __forceinline__ void cp_async16(u32 dst, const void* src, bool valid) {
    int sz = valid ? 16 : 0;
    asm volatile("cp.async.cg.shared.global [%0], [%1], 16, %2;"
                 :: "r"(dst), "l"(src), "r"(sz) : "memory");
}
__device__ __forceinline__ void cp_commit() {
    asm volatile("cp.async.commit_group;" ::: "memory");
}
template <int N>
__device__ __forceinline__ void cp_wait() {
    asm volatile("cp.async.wait_group %0;" :: "n"(N) : "memory");
}
#define LDMX4(r0, r1, r2, r3, addr) \
    asm volatile("ldmatrix.sync.aligned.m8n8.x4.shared.b16 {%0,%1,%2,%3}, [%4];" \
                 : "=r"(r0), "=r"(r1), "=r"(r2), "=r"(r3) : "r"(addr))

__device__ __forceinline__ void mma_bf16(float* c, const u32* a, const u32* b) {
    asm volatile(
        "mma.sync.aligned.m16n8k16.row.col.f32.bf16.bf16.f32 "
        "{%0,%1,%2,%3}, {%4,%5,%6,%7}, {%8,%9}, {%0,%1,%2,%3};"
        : "+f"(c[0]), "+f"(c[1]), "+f"(c[2]), "+f"(c[3])
        : "r"(a[0]), "r"(a[1]), "r"(a[2]), "r"(a[3]), "r"(b[0]), "r"(b[1]));
}

__device__ __forceinline__ void split_bf16(float v, __nv_bfloat16& h, __nv_bfloat16& l) {
    h = __float2bfloat16_rn(v);
    l = __float2bfloat16_rn(v - __bfloat162float(h));
}
__device__ __forceinline__ int swidx(int co, int ci) {
    int ub = co * 128 + (ci >> 3) * 16;
    int sw = ub ^ ((ub >> 3) & 0x70);
    return (sw >> 1) + (ci & 7);
}
__device__ __forceinline__ u32 swz(u32 b) { return b ^ ((b >> 3) & 0x70); }

// ============================================================================
// Prep kernels
// ============================================================================
__global__ void prep_weights(const float* __restrict__ W0,
                             const float* __restrict__ Wd1,
                             const float* __restrict__ W1a,
                             const float* __restrict__ W1b,
                             const float* __restrict__ Wd2,
                             const float* __restrict__ mask)
{
    const int gid = blockIdx.x * blockDim.x + threadIdx.x;
    const int gs = gridDim.x * blockDim.x;

    for (int i = gid; i < 54 * 4096; i += gs) {
        int chunk = i >> 12, r = i & 4095, co = r >> 6, ci = r & 63;
        int cc = chunk & 1, tap = chunk >> 1;
        int kw = tap % 3, kh = (tap / 3) % 3, kd = tap / 9;
        float v = W0[(size_t)(co * 128 + cc * 64 + ci) * 27 + kd * 9 + kh * 3 + kw];
        __nv_bfloat16 h, l; split_bf16(v, h, l);
        int dst = chunk * 4096 + swidx(co, ci);
        g_B0h[dst] = h; g_B0l[dst] = l;
    }
    for (int i = gid; i < 27 * 4096; i += gs) {
        int chunk = i >> 12, r = i & 4095, co = r >> 6, ci = r & 63;
        int kw = chunk % 3, kh = (chunk / 3) % 3, kd = chunk / 9;
        size_t src = (size_t)(co * 64 + ci) * 27 + kd * 9 + kh * 3 + kw;
        int dst = chunk * 4096 + swidx(co, ci);
        __nv_bfloat16 h, l;
        split_bf16(W1a[src], h, l); g_B1ah[dst] = h; g_B1al[dst] = l;
        split_bf16(W1b[src], h, l); g_B1bh[dst] = h; g_B1bl[dst] = l;
    }
    for (int i = gid; i < 3 * 4096; i += gs) {
        int chunk = i >> 12, r = i & 4095, co = r >> 6, ci = r & 63;
        size_t src = (size_t)(co * 64 + ci) * 3 + chunk;
        int dst = chunk * 4096 + swidx(co, ci);
        __nv_bfloat16 h, l;
        split_bf16(Wd1[src], h, l); g_Bd1h[dst] = h; g_Bd1l[dst] = l;
        split_bf16(Wd2[src], h, l); g_Bd2h[dst] = h; g_Bd2l[dst] = l;
    }
    for (int i = gid; i < 20 * HW; i += gs) {
        int dp = i >> 14, r = i & 16383;
        float a = mask[(size_t)(2 * dp) * HW + r];
        float b = mask[(size_t)(2 * dp + 1) * HW + r];
        float c = mask[(size_t)(2 * dp + 2) * HW + r];
        g_m2[i] = (fmaxf(a, fmaxf(b, c)) > 0.5f) ? 1.0f : 0.0f;
    }
}

__global__ void __launch_bounds__(256) conv0_pre(const float* __restrict__ feat,
                                                 const float* __restrict__ mask)
{
    const int h = blockIdx.x, d = blockIdx.y;
    const int tid = threadIdx.x;
    __shared__ float t[32][129];
    __shared__ float mrow[128];

    const size_t row0 = ((size_t)d * 128 + h) * 128;
    if (tid < 128) {
        float mv = mask[row0 + tid] > 0.5f ? 1.0f : 0.0f;
        mrow[tid] = mv;
        g_m0[row0 + tid] = mv;
    }
    __syncthreads();

    for (int cc = 0; cc < 4; ++cc) {
        #pragma unroll 1
        for (int i = tid; i < 32 * 128; i += 256) {
            int ci = i >> 7, w = i & 127;
            t[ci][w] = feat[((size_t)(cc * 32 + ci) * 41 + d) * HW + h * 128 + w];
        }
        __syncthreads();
        #pragma unroll 1
        for (int i = tid; i < 128 * 16; i += 256) {
            int w = i >> 4, p = i & 15;
            float mv = mrow[w];
            float v0 = t[p * 2][w] * mv;
            float v1 = t[p * 2 + 1][w] * mv;
            __nv_bfloat16 h0, l0, h1, l1;
            split_bf16(v0, h0, l0);
            split_bf16(v1, h1, l1);
            __nv_bfloat162 hh(h0, h1), ll(l0, l1);
            size_t base = (row0 + w) * 128 + cc * 32;
            *(__nv_bfloat162*)(g_x0h + base + p * 2) = hh;
            *(__nv_bfloat162*)(g_x0l + base + p * 2) = ll;
        }
        __syncthreads();
    }
}

// ============================================================================
// 3x3x3 SAME subm conv: kw in the compute loop (A staged once with w-halo).
// 512 threads, 16 warps: warp_m = wid&7 (m16), warp_n = wid>>3 (n32).
// Stage = A halo tile (130 rows x 64ci, hi+lo = 33KB) + 3 kw B tiles (48KB).
// Double buffered: 165.9KB dynamic smem, 1 CTA/SM.
// ============================================================================
#define A_SPLIT 16896                     // 132 rows * 128B
#define STAGE_A (2 * A_SPLIT)             // 33792
#define STAGE_B (6 * 8192)                // 49152 (3 kw x hi/lo)
#define STAGEB (STAGE_A + STAGE_B)        // 82944
#define SMEM_SUBM (2 * STAGEB)            // 165888

template <int CC, bool OMASK>
__global__ void __launch_bounds__(512)
subm_mma_kernel(const __nv_bfloat16* __restrict__ in_hi,
                const __nv_bfloat16* __restrict__ in_lo,
                const __nv_bfloat16* __restrict__ w_hi,
                const __nv_bfloat16* __restrict__ w_lo,
                const float* __restrict__ omask,
                __nv_bfloat16* __restrict__ out_hi,
                __nv_bfloat16* __restrict__ out_lo,
                int Din)
{
    extern __shared__ char smem[];
    const u32 smem_base = smem_u32(smem);
    const int tid = threadIdx.x;
    const int wid = tid >> 5;
    const int lane = tid & 31;
    const int h = blockIdx.x;
    const int dz = blockIdx.y;
    const int CITOT = CC * 64;
    const int warp_m = wid & 7;
    const int warp_n = wid >> 3;

    __shared__ int s_din[18];
    __shared__ int s_aux[18];   // hin | cc<<8 | wbase<<12
    __shared__ int s_n;
    __shared__ float s_mask[128];

    if (tid == 0) {
        int n = 0;
        for (int kd = 0; kd < 3; ++kd) {
            int din = dz + kd - 1;
            if (din < 0 || din >= Din) continue;
            for (int kh = 0; kh < 3; ++kh) {
                int hin = h + kh - 1;
                if ((unsigned)hin > 127u) continue;
                for (int cc = 0; cc < CC; ++cc) {
                    int wbase = ((kd * 3 + kh) * 3) * CC + cc;  // kw=0 tile
                    s_din[n] = din;
                    s_aux[n] = hin | (cc << 8) | (wbase << 12);
                    ++n;
                }
            }
        }
        s_n = n;
    }
    if (OMASK && tid < 128)
        s_mask[tid] = omask[((size_t)dz * 128 + h) * 128 + tid];
    __syncthreads();
    const int nch = s_n;

    // ldmatrix A addressing: base row r; kw shifts row by +kw (halo offset +1
    // already folded in: stored row = win+1, fragment row for output m under
    // kw is win = m+kw-1 -> stored row = m+kw).
    u32 a_rowk[3], a_sxk[3];
    {
        int r = warp_m * 16 + (lane & 7) + ((lane >> 3) & 1) * 8;
        #pragma unroll
        for (int kw = 0; kw < 3; ++kw) {
            a_rowk[kw] = (u32)(r + kw) * 128;
            a_sxk[kw] = (u32)((r + kw) & 7) << 4;
        }
    }
    const u32 a_c = (u32)(lane >> 4) * 16;

    u32 b_row[2], b_sx[2];
    #pragma unroll
    for (int nh = 0; nh < 2; ++nh) {
        int rown = warp_n * 32 + nh * 16 + (lane & 7) + (lane >> 4) * 8;
        b_row[nh] = (u32)rown * 128;
        b_sx[nh] = (u32)(rown & 7) << 4;
    }
    const u32 b_c = (u32)((lane >> 3) & 1) * 16;

    float acc[4][4];
    #pragma unroll
    for (int nt = 0; nt < 4; ++nt)
        #pragma unroll
        for (int q = 0; q < 4; ++q) acc[nt][q] = 0.0f;

    // ---- staging ----
    auto stage = [&](int i, int buf) {
        const int din = s_din[i];
        const int aux = s_aux[i];
        const int hin = aux & 255;
        const int cc = (aux >> 8) & 15;
        const int wb = aux >> 12;
        const u32 base = smem_base + buf * STAGEB;
        // A: 130 rows (win=-1..128) x 64ci x hi/lo
        #pragma unroll 1
        for (int t = tid; t < 2080; t += 512) {
            int sp2 = t >= 1040;
            int u = sp2 ? t - 1040 : t;
            int row = u >> 3, seg = u & 7;
            int win = row - 1;
            bool valid = (unsigned)win < 128u;
            const char* src = (const char*)((sp2 ? in_lo : in_hi) +
                (((size_t)din * 128 + hin) * 128 + (valid ? win : 0)) * CITOT +
                cc * 64) + seg * 16;
            cp_async16(base + sp2 * A_SPLIT + swz(row * 128 + seg * 16), src, valid);
        }
        // B: 3 kw tiles x hi/lo (pre-swizzled, straight copy)
        #pragma unroll 1
        for (int t = tid; t < 3072; t += 512) {
            int tile = t >> 9, idx = t & 511;
            int kw = tile >> 1, sp2 = tile & 1;
            const char* src = (const char*)((sp2 ? w_lo : w_hi) +
                (size_t)(wb + kw * CC) * 4096) + idx * 16;
            cp_async16(base + STAGE_A + kw * 16384 + sp2 * 8192 + idx * 16, src, true);
        }
        cp_commit();
    };

    stage(0, 0);
    for (int i = 0; i < nch; ++i) {
        const int buf = i & 1;
        if (i + 1 < nch) { stage(i + 1, buf ^ 1); cp_wait<1>(); }
        else             { cp_wait<0>(); }
        __syncthreads();

        const u32 ahi = smem_base + buf * STAGEB;
        const u32 alo = ahi + A_SPLIT;
        const u32 bb = smem_base + buf * STAGEB + STAGE_A;

        #pragma unroll
        for (int kw = 0; kw < 3; ++kw) {
            const u32 bhi = bb + kw * 16384;
            const u32 blo = bhi + 8192;
            #pragma unroll
            for (int k16 = 0; k16 < 4; ++k16) {
                const u32 ko = k16 * 32;
                const u32 aoff = a_rowk[kw] + ((a_c + ko) ^ a_sxk[kw]);
                u32 A0[4], A1[4];
                LDMX4(A0[0], A0[1], A0[2], A0[3], ahi + aoff);
                LDMX4(A1[0], A1[1], A1[2], A1[3], alo + aoff);
                u32 B0[4][2], B1[4][2];
                #pragma unroll
                for (int nh = 0; nh < 2; ++nh) {
                    const u32 boff = b_row[nh] + ((b_c + ko) ^ b_sx[nh]);
                    LDMX4(B0[2*nh][0], B0[2*nh][1], B0[2*nh+1][0], B0[2*nh+1][1],
                          bhi + boff);
                    LDMX4(B1[2*nh][0], B1[2*nh][1], B1[2*nh+1][0], B1[2*nh+1][1],
                          blo + boff);
                }
                #pragma unroll
                for (int nt = 0; nt < 4; ++nt) {
                    mma_bf16(acc[nt], A0, B0[nt]);  // hi*hi
                    mma_bf16(acc[nt], A0, B1[nt]);  // hi*lo
                    mma_bf16(acc[nt], A1, B0[nt]);  // lo*hi
                }
            }
        }
        __syncthreads();
    }

    // ---- epilogue ----
    const int g = lane >> 2, tg = lane & 3;
    #pragma unroll
    for (int half = 0; half < 2; ++half) {
        const int m = warp_m * 16 + g + half * 8;
        const float mv = OMASK ? s_mask[m] : 1.0f;
        const size_t row = ((size_t)dz * 128 + h) * 128 + m;
        #pragma unroll
        for (int nt = 0; nt < 4; ++nt) {
            const int n0 = warp_n * 32 + nt * 8 + tg * 2;
            float v0 = fmaxf(acc[nt][half * 2 + 0] * mv, 0.0f);
            float v1 = fmaxf(acc[nt][half * 2 + 1] * mv, 0.0f);
            __nv_bfloat16 h0, l0, h1, l1;
            split_bf16(v0, h0, l0);
            split_bf16(v1, h1, l1);
            __nv_bfloat162 hh(h0, h1), ll(l0, l1);
            *(u32*)(out_hi + row * 64 + n0) = *(u32*)&hh;
            *(u32*)(out_lo + row * 64 + n0) = *(u32*)&ll;
        }
    }
}

// ============================================================================
// (3,1,1) stride-(2,1,1) down conv (proven R4 kernel, K333 stripped out).
// ============================================================================
#define ABYTES 32768
#define BBYTES 16384
#define BUFB (ABYTES + BBYTES)
#define SMEM_DOWN (2 * BUFB)

template <bool FP32OUT>
__global__ void __launch_bounds__(256)
down_mma_kernel(const __nv_bfloat16* __restrict__ in_hi,
                const __nv_bfloat16* __restrict__ in_lo,
                const __nv_bfloat16* __restrict__ w_hi,
                const __nv_bfloat16* __restrict__ w_lo,
                __nv_bfloat16* __restrict__ out_hi,
                __nv_bfloat16* __restrict__ out_lo,
                float* __restrict__ out_f32,
                int Dout)
{
    extern __shared__ char smem[];
    const u32 smem_base = smem_u32(smem);
    const int tid = threadIdx.x;
    const int wid = tid >> 5;
    const int lane = tid & 31;
    const int h = blockIdx.x;
    const int dz = blockIdx.y;
    const int warp_m = wid & 3;
    const int warp_n = wid >> 2;

    const int sp = tid >> 7;
    const int mrow = tid & 127;
    const __nv_bfloat16* xin = sp ? in_lo : in_hi;
    const __nv_bfloat16* wsrc = sp ? w_lo : w_hi;

    u32 a_st[8];
    #pragma unroll
    for (int u = 0; u < 8; ++u)
        a_st[u] = swz(mrow * 128 + u * 16);

    u32 a_row[2], a_sx[2];
    #pragma unroll
    for (int mt = 0; mt < 2; ++mt) {
        int row = warp_m * 32 + mt * 16 + (lane & 7) + ((lane >> 3) & 1) * 8;
        a_row[mt] = (u32)row * 128;
        a_sx[mt] = (u32)(row & 7) << 4;
    }
    const u32 a_c = (u32)(lane >> 4) * 16;

    u32 b_row[2], b_sx[2];
    #pragma unroll
    for (int nh = 0; nh < 2; ++nh) {
        int rown = warp_n * 32 + nh * 16 + (lane & 7) + (lane >> 4) * 8;
        b_row[nh] = (u32)rown * 128;
        b_sx[nh] = (u32)(rown & 7) << 4;
    }
    const u32 b_c = (u32)((lane >> 3) & 1) * 16;

    float acc[2][4][4];
    #pragma unroll
    for (int mt = 0; mt < 2; ++mt)
        #pragma unroll
        for (int nt = 0; nt < 4; ++nt)
            #pragma unroll
            for (int q = 0; q < 4; ++q) acc[mt][nt][q] = 0.0f;

    auto stage = [&](int kd, int buf) {
        const int din = 2 * dz + kd;
        const u32 abase = smem_base + buf * BUFB + sp * 16384;
        const char* src = (const char*)(xin +
            (((size_t)din * 128 + h) * 128 + mrow) * 64);
        #pragma unroll
        for (int u = 0; u < 8; ++u)
            cp_async16(abase + a_st[u], src + u * 16, true);

        const u32 bbase = smem_base + buf * BUFB + ABYTES + sp * 8192;
        const char* gb = (const char*)(wsrc + (size_t)kd * 4096);
        const int j = tid & 127;
        #pragma unroll
        for (int u = 0; u < 4; ++u)
            cp_async16(bbase + (j + u * 128) * 16, gb + (j + u * 128) * 16, true);
        cp_commit();
    };

    stage(0, 0);
    for (int i = 0; i < 3; ++i) {
        const int buf = i & 1;
        if (i + 1 < 3) { stage(i + 1, buf ^ 1); cp_wait<1>(); }
        else           { cp_wait<0>(); }
        __syncthreads();

        const u32 ahi = smem_base + buf * BUFB;
        const u32 alo = ahi + 16384;
        const u32 bhi = smem_base + buf * BUFB + ABYTES;
        const u32 blo = bhi + 8192;

        #pragma unroll
        for (int k16 = 0; k16 < 4; ++k16) {
            const u32 ko = k16 * 32;
            u32 A0[2][4], A1[2][4];
            #pragma unroll
            for (int mt = 0; mt < 2; ++mt) {
                const u32 aoff = a_row[mt] + ((a_c + ko) ^ a_sx[mt]);
                LDMX4(A0[mt][0], A0[mt][1], A0[mt][2], A0[mt][3], ahi + aoff);
                LDMX4(A1[mt][0], A1[mt][1], A1[mt][2], A1[mt][3], alo + aoff);
            }
            u32 B0[4][2], B1[4][2];
            #pragma unroll
            for (int nh = 0; nh < 2; ++nh) {
                const u32 boff = b_row[nh] + ((b_c + ko) ^ b_sx[nh]);
                LDMX4(B0[2*nh][0], B0[2*nh][1], B0[2*nh+1][0], B0[2*nh+1][1],
                      bhi + boff);
                LDMX4(B1[2*nh][0], B1[2*nh][1], B1[2*nh+1][0], B1[2*nh+1][1],
                      blo + boff);
            }
            #pragma unroll
            for (int mt = 0; mt < 2; ++mt)
                #pragma unroll
                for (int nt = 0; nt < 4; ++nt) {
                    mma_bf16(acc[mt][nt], A0[mt], B0[nt]);
                    mma_bf16(acc[mt][nt], A0[mt], B1[nt]);
                    mma_bf16(acc[mt][nt], A1[mt], B0[nt]);
                }
        }
        __syncthreads();
    }

    const int g = lane >> 2, tg = lane & 3;
    #pragma unroll
    for (int mt = 0; mt < 2; ++mt) {
        #pragma unroll
        for (int half = 0; half < 2; ++half) {
            const int m = warp_m * 32 + mt * 16 + g + half * 8;
            const size_t row = ((size_t)dz * 128 + h) * 128 + m;
            #pragma unroll
            for (int nt = 0; nt < 4; ++nt) {
                const int n0 = warp_n * 32 + nt * 8 + tg * 2;
                float v0 = fmaxf(acc[mt][nt][half * 2 + 0], 0.0f);
                float v1 = fmaxf(acc[mt][nt][half * 2 + 1], 0.0f);
                if (FP32OUT) {
                    out_f32[((size_t)n0 * Dout + dz) * HW + h * 128 + m] = v0;
                    out_f32[((size_t)(n0 + 1) * Dout + dz) * HW + h * 128 + m] = v1;
                } else {
                    __nv_bfloat16 h0, l0, h1, l1;
                    split_bf16(v0, h0, l0);
                    split_bf16(v1, h1, l1);
                    __nv_bfloat162 hh(h0, h1), ll(l0, l1);
                    *(u32*)(out_hi + row * 64 + n0) = *(u32*)&hh;
                    *(u32*)(out_lo + row * 64 + n0) = *(u32*)&ll;
                }
            }
        }
    }
}

// ============================================================================
extern "C" void kernel_launch(void* const* d_in, const int* in_sizes, int n_in,
                              void* d_out, int out_size)
{
    const float* feat = (const float*)d_in[0];
    const float* mask = (const float*)d_in[1];
    const float* W0   = (const float*)d_in[2];
    const float* Wd1  = (const float*)d_in[3];
    const float* W1a  = (const float*)d_in[4];
    const float* W1b  = (const float*)d_in[5];
    const float* Wd2  = (const float*)d_in[6];
    float* out = (float*)d_out;

    void* p;
    #define SYM(v, s) cudaGetSymbolAddress(&p, s); auto* v = (decltype(&s[0]))p;
    SYM(x0h, g_x0h) SYM(x0l, g_x0l)
    SYM(x1h, g_x1h) SYM(x1l, g_x1l)
    SYM(x2h, g_x2h) SYM(x2l, g_x2l)
    SYM(x3h, g_x3h) SYM(x3l, g_x3l)
    SYM(m0, g_m0)   SYM(m2, g_m2)
    SYM(b0h, g_B0h)   SYM(b0l, g_B0l)
    SYM(b1ah, g_B1ah) SYM(b1al, g_B1al)
    SYM(b1bh, g_B1bh) SYM(b1bl, g_B1bl)
    SYM(bd1h, g_Bd1h) SYM(bd1l, g_Bd1l)
    SYM(bd2h, g_Bd2h) SYM(bd2l, g_Bd2l)
    #undef SYM

    cudaFuncSetAttribute(subm_mma_kernel<2, true>,
                         cudaFuncAttributeMaxDynamicSharedMemorySize, SMEM_SUBM);
    cudaFuncSetAttribute(subm_mma_kernel<1, true>,
                         cudaFuncAttributeMaxDynamicSharedMemorySize, SMEM_SUBM);
    cudaFuncSetAttribute(down_mma_kernel<false>,
                         cudaFuncAttributeMaxDynamicSharedMemorySize, SMEM_DOWN);
    cudaFuncSetAttribute(down_mma_kernel<true>,
                         cudaFuncAttributeMaxDynamicSharedMemorySize, SMEM_DOWN);

    prep_weights<<<264, 256>>>(W0, Wd1, W1a, W1b, Wd2, mask);
    conv0_pre<<<dim3(128, 41), 256>>>(feat, mask);

    // conv0: 128->64, 3x3x3 SAME, output masked by m0 (input pre-masked)
    subm_mma_kernel<2, true><<<dim3(128, 41), 512, SMEM_SUBM>>>(
        x0h, x0l, b0h, b0l, m0, x1h, x1l, 41);
    // down1: (3,1,1)/stride(2,1,1), relu
    down_mma_kernel<false><<<dim3(128, 20), 256, SMEM_DOWN>>>(
        x1h, x1l, bd1h, bd1l, x2h, x2l, nullptr, 20);
    // subm1a / subm1b: 3x3x3 SAME, output masked by m2
    subm_mma_kernel<1, true><<<dim3(128, 20), 512, SMEM_SUBM>>>(
        x2h, x2l, b1ah, b1al, m2, x3h, x3l, 20);
    subm_mma_kernel<1, true><<<dim3(128, 20), 512, SMEM_SUBM>>>(
        x3h, x3l, b1bh, b1bl, m2, x1h, x1l, 20);
    // down2 -> fp32 NCDHW output
    down_mma_kernel<true><<<dim3(128, 9), 256, SMEM_DOWN>>>(
        x1h, x1l, bd2h, bd2l, nullptr, nullptr, out, 9);
}